// round 7
// baseline (speedup 1.0000x reference)
#include <cuda_runtime.h>
#include <stdint.h>
#include <math.h>

// Problem constants (fixed by dataset)
#define MAXN     100000
#define FIN      128
#define HID      64
#define NBW      ((MAXN + 31) / 32)   // 3125 bitmap words = 12.5 KB
#define MAXSLOTS 16384                // |V1| bound (actual ~2.1k)
#define MAXL2    65536                // layer-2 edge bound (actual ~2k)
#define SCAN_BLOCKS  1184
#define SCAN_THREADS 256

// ---------------- static device scratch (zero at entry; tail re-zeroes) -----
__device__ int      d_deg[MAXN];
__device__ unsigned d_isout_bits[NBW];
__device__ unsigned d_need_bits[NBW];
__device__ int      d_slot[MAXN];               // node -> slot (valid iff need bit)
__device__ int      d_slotnode[MAXSLOTS];       // slot -> node
__device__ __align__(16) float d_xagg[(size_t)MAXSLOTS * FIN]; // rows zeroed lazily
__device__ float    d_tval[MAXSLOTS];           // relu(h1)@W2 per slot
__device__ float    d_sdinv[MAXSLOTS];          // dinv per slot
__device__ int2     d_l2[MAXL2];                // edges into output nodes
__device__ int      d_nslots;
__device__ int      d_nl2;

__device__ __forceinline__ void red_add_v4(float* addr, float a, float b, float c, float d) {
    asm volatile("red.global.add.v4.f32 [%0], {%1,%2,%3,%4};"
                 :: "l"(addr), "f"(a), "f"(b), "f"(c), "f"(d) : "memory");
}
__device__ __forceinline__ int test_bit(const unsigned* bits, int i) {
    return (bits[i >> 5] >> (i & 31)) & 1u;
}
__device__ __forceinline__ void zero_row(int s) {
    float4* row = (float4*)&d_xagg[(size_t)s * FIN];
    #pragma unroll
    for (int k = 0; k < FIN / 4; k++) row[k] = make_float4(0.f, 0.f, 0.f, 0.f);
}

// ---------------------------------------------------------------------------
// Mark output nodes (last of each graph, batch sorted); init out[] with bias.
__global__ void k_mark(const int* __restrict__ batch, int N,
                       float* __restrict__ out, const float* __restrict__ b2, int G) {
    int i = blockIdx.x * blockDim.x + threadIdx.x;
    if (i < G) out[i] = b2[0];
    if (i >= N) return;
    bool last = (i == N - 1) || (batch[i] != batch[i + 1]);
    if (last) {
        atomicOr(&d_isout_bits[i >> 5], 1u << (i & 31));
        atomicOr(&d_need_bits[i >> 5], 1u << (i & 31));
        int s = atomicAdd(&d_nslots, 1);
        if (s < MAXSLOTS) { d_slot[i] = s; d_slotnode[s] = i; zero_row(s); }
    }
}

// pass1: deg histogram (RED) + collect layer-2 edges + extend V1 slot set.
// isout bitmap staged in smem -> probes are LDS, not 27-wavefront LDGs.
__device__ __forceinline__ void pass1_hit(int sj, int dj) {
    int p = atomicAdd(&d_nl2, 1);
    if (p < MAXL2) d_l2[p] = make_int2(sj, dj);
    unsigned bit = 1u << (sj & 31);
    unsigned old = atomicOr(&d_need_bits[sj >> 5], bit);
    if (!(old & bit)) {                              // winner assigns + zeroes
        int s = atomicAdd(&d_nslots, 1);
        if (s < MAXSLOTS) { d_slot[sj] = s; d_slotnode[s] = sj; zero_row(s); }
    }
}

__global__ void __launch_bounds__(SCAN_THREADS)
k_pass1(const int* __restrict__ src, const int4* __restrict__ dst4, int E4) {
    __shared__ unsigned sb[NBW];
    for (int i = threadIdx.x; i < NBW; i += blockDim.x) sb[i] = d_isout_bits[i];
    __syncthreads();
    int gstride = gridDim.x * blockDim.x;
    for (int j = blockIdx.x * blockDim.x + threadIdx.x; j < E4; j += gstride) {
        int4 d = __ldg(&dst4[j]);
        atomicAdd(&d_deg[d.x], 1);
        atomicAdd(&d_deg[d.y], 1);
        atomicAdd(&d_deg[d.z], 1);
        atomicAdd(&d_deg[d.w], 1);
        if (test_bit(sb, d.x)) pass1_hit(__ldg(&src[4 * j + 0]), d.x);
        if (test_bit(sb, d.y)) pass1_hit(__ldg(&src[4 * j + 1]), d.y);
        if (test_bit(sb, d.z)) pass1_hit(__ldg(&src[4 * j + 2]), d.z);
        if (test_bit(sb, d.w)) pass1_hit(__ldg(&src[4 * j + 3]), d.w);
    }
}
// scalar fallback
__global__ void k_pass1_s(const int* __restrict__ src, const int* __restrict__ dst, int E) {
    int gstride = gridDim.x * blockDim.x;
    for (int i = blockIdx.x * blockDim.x + threadIdx.x; i < E; i += gstride) {
        int dj = __ldg(&dst[i]);
        atomicAdd(&d_deg[dj], 1);
        if (test_bit(d_isout_bits, dj)) pass1_hit(__ldg(&src[i]), dj);
    }
}

// scatter: scan edges; matched (dst in V1) -> warp-cooperative red.v4 of
// x[src]*dinv[src] into xagg[slot[dst]]. need bitmap staged in smem.
__global__ void __launch_bounds__(SCAN_THREADS)
k_scatter(const int* __restrict__ src, const int4* __restrict__ dst4,
          const float4* __restrict__ x4, int E4) {
    __shared__ unsigned sb[NBW];
    for (int i = threadIdx.x; i < NBW; i += blockDim.x) sb[i] = d_need_bits[i];
    __syncthreads();
    int lane   = threadIdx.x & 31;
    int wglob  = (blockIdx.x * blockDim.x + threadIdx.x) >> 5;
    int nwarps = (gridDim.x * blockDim.x) >> 5;
    for (int base = wglob * 32; base < E4; base += nwarps * 32) {
        int j = base + lane;
        bool in = j < E4;
        int4 d = make_int4(0, 0, 0, 0);
        if (in) d = __ldg(&dst4[j]);
        #pragma unroll
        for (int c = 0; c < 4; c++) {
            int dj = (c == 0) ? d.x : (c == 1) ? d.y : (c == 2) ? d.z : d.w;
            int pred = in && test_bit(sb, dj);
            int sj = 0, sl = 0;
            float w = 0.f;
            if (pred) {
                sj = __ldg(&src[4 * j + c]);
                sl = d_slot[dj];
                w  = rsqrtf((float)(__ldg(&d_deg[sj]) + 1));
            }
            unsigned m = __ballot_sync(0xffffffffu, pred);
            while (m) {
                int b = __ffs(m) - 1;
                m &= m - 1;
                int   bs  = __shfl_sync(0xffffffffu, sj, b);
                int   bsl = __shfl_sync(0xffffffffu, sl, b);
                float bw  = __shfl_sync(0xffffffffu, w,  b);
                float4 xv = __ldg(&x4[(size_t)bs * (FIN / 4) + lane]);
                red_add_v4(&d_xagg[(size_t)bsl * FIN + lane * 4],
                           xv.x * bw, xv.y * bw, xv.z * bw, xv.w * bw);
            }
        }
    }
}
// scalar fallback
__global__ void k_scatter_s(const int* __restrict__ src, const int* __restrict__ dst,
                            const float4* __restrict__ x4, int E) {
    int lane   = threadIdx.x & 31;
    int wglob  = (blockIdx.x * blockDim.x + threadIdx.x) >> 5;
    int nwarps = (gridDim.x * blockDim.x) >> 5;
    for (int base = wglob * 32; base < E; base += nwarps * 32) {
        int j = base + lane;
        bool in = j < E;
        int dj = 0, sj = 0, sl = 0;
        float w = 0.f;
        int pred = 0;
        if (in) { dj = __ldg(&dst[j]); pred = test_bit(d_need_bits, dj); }
        if (pred) {
            sj = __ldg(&src[j]);
            sl = d_slot[dj];
            w  = rsqrtf((float)(__ldg(&d_deg[sj]) + 1));
        }
        unsigned m = __ballot_sync(0xffffffffu, pred);
        while (m) {
            int b = __ffs(m) - 1;
            m &= m - 1;
            int   bs  = __shfl_sync(0xffffffffu, sj, b);
            int   bsl = __shfl_sync(0xffffffffu, sl, b);
            float bw  = __shfl_sync(0xffffffffu, w,  b);
            float4 xv = __ldg(&x4[(size_t)bs * (FIN / 4) + lane]);
            red_add_v4(&d_xagg[(size_t)bsl * FIN + lane * 4],
                       xv.x * bw, xv.y * bw, xv.z * bw, xv.w * bw);
        }
    }
}

// block per slot: y = xagg*dv + x[v]*dv^2 ; h1 = relu(y@W1+b1) ; tval = h1@W2
// plus layer-2 self-loop term.
__global__ void __launch_bounds__(FIN) k_compute(const float* __restrict__ x,
                          const float* __restrict__ W1,
                          const float* __restrict__ b1,
                          const float* __restrict__ W2,
                          const int*   __restrict__ batch,
                          float* __restrict__ out) {
    __shared__ float ysh[FIN];
    __shared__ float redsh[HID];
    int ns = d_nslots; if (ns > MAXSLOTS) ns = MAXSLOTS;
    int t  = threadIdx.x;   // 0..127, feature index
    for (int s = blockIdx.x; s < ns; s += gridDim.x) {
        int v = d_slotnode[s];
        float dv = rsqrtf((float)(d_deg[v] + 1));
        ysh[t] = d_xagg[(size_t)s * FIN + t] * dv
               + __ldg(&x[(size_t)v * FIN + t]) * dv * dv;
        if (t == 0) d_sdinv[s] = dv;
        __syncthreads();
        if (t < HID) {
            float h = b1[t];
            #pragma unroll 16
            for (int k = 0; k < FIN; k++)
                h = fmaf(ysh[k], W1[k * HID + t], h);
            h = fmaxf(h, 0.f);
            redsh[t] = h * W2[t];
        }
        __syncthreads();
        if (t < 32) {
            float p = redsh[t] + redsh[t + 32];
            #pragma unroll
            for (int o = 16; o > 0; o >>= 1)
                p += __shfl_down_sync(0xffffffffu, p, o);
            if (t == 0) {
                d_tval[s] = p;
                if (test_bit(d_isout_bits, v))      // layer-2 self-loop term
                    atomicAdd(&out[batch[v]], p * dv * dv);
            }
        }
        __syncthreads();
    }
}

// block 0: layer-2 edge reduce; all blocks: zero scratch for the next call
__global__ void k_final(const int* __restrict__ batch, float* __restrict__ out) {
    int i = blockIdx.x * blockDim.x + threadIdx.x;
    if (blockIdx.x == 0) {
        int n1 = d_nl2; if (n1 > MAXL2) n1 = MAXL2;
        for (int k = threadIdx.x; k < n1; k += blockDim.x) {
            int2 e = d_l2[k];
            int ss = d_slot[e.x];
            int sd = d_slot[e.y];
            atomicAdd(&out[batch[e.y]], d_tval[ss] * d_sdinv[ss] * d_sdinv[sd]);
        }
        __syncthreads();
        if (threadIdx.x == 0) { d_nl2 = 0; d_nslots = 0; }
    }
    if (i < MAXN) d_deg[i] = 0;
    if (i < NBW) { d_isout_bits[i] = 0u; d_need_bits[i] = 0u; }
}

// ---------------------------------------------------------------------------
extern "C" void kernel_launch(void* const* d_in, const int* in_sizes, int n_in,
                              void* d_out, int out_size) {
    const float* x     = (const float*)d_in[0];
    const int*   ei    = (const int*)  d_in[1];
    const int*   batch = (const int*)  d_in[2];
    const float* W1    = (const float*)d_in[3];
    const float* b1    = (const float*)d_in[4];
    const float* W2    = (const float*)d_in[5];
    const float* b2    = (const float*)d_in[6];
    float* out = (float*)d_out;

    const int N = in_sizes[2];
    const int E = in_sizes[1] / 2;
    const int G = out_size;

    const int* src = ei;
    const int* dst = ei + E;

    int gN = (N + 255) / 256;

    k_mark<<<gN, 256>>>(batch, N, out, b2, G);

    bool vec_ok = ((E & 3) == 0) &&
                  ((((uintptr_t)src) & 15) == 0) && ((((uintptr_t)dst) & 15) == 0);
    if (vec_ok) {
        int E4 = E / 4;
        k_pass1  <<<SCAN_BLOCKS, SCAN_THREADS>>>(src, (const int4*)dst, E4);
        k_scatter<<<SCAN_BLOCKS, SCAN_THREADS>>>(src, (const int4*)dst,
                                                 (const float4*)x, E4);
    } else {
        k_pass1_s  <<<SCAN_BLOCKS, SCAN_THREADS>>>(src, dst, E);
        k_scatter_s<<<SCAN_BLOCKS, SCAN_THREADS>>>(src, dst, (const float4*)x, E);
    }

    k_compute<<<2048, FIN>>>(x, W1, b1, W2, batch, out);
    k_final  <<<gN, 256>>>(batch, out);
}